// round 15
// baseline (speedup 1.0000x reference)
#include <cuda_runtime.h>
#include <cuda_fp16.h>
#include <cstdint>

#define N_NODES 100000
#define N_EDGES 3200000
#define IN_SIZE 256
#define HID_SIZE 256
#define OUT_SIZE 64

// -------- scratch (no allocations allowed -> __device__ globals) --------
__device__ __align__(1024) __half g_xw1[(size_t)N_NODES * HID_SIZE];  // X @ W1
__device__ __align__(1024) __half g_h  [(size_t)N_NODES * HID_SIZE];  // relu(A@XW1+b1)
__device__ __align__(1024) __half g_hw2[(size_t)N_NODES * OUT_SIZE];  // h @ W2
__device__ __align__(1024) __half g_w1t[(size_t)HID_SIZE * IN_SIZE];  // W1^T [n][k]
__device__ __align__(1024) __half g_w2t[(size_t)OUT_SIZE * HID_SIZE]; // W2^T [n][k]
__device__ int    g_rowptr[N_NODES + 1];

// -------- CSR row_ptr from sorted COO row[]: per-node lower_bound --------
__global__ void build_rowptr_kernel(const int* __restrict__ row) {
    int r = blockIdx.x * blockDim.x + threadIdx.x;
    if (r > N_NODES) return;
    int lo = 0, hi = N_EDGES;
    while (lo < hi) {
        int mid = (lo + hi) >> 1;
        if (row[mid] < r) lo = mid + 1; else hi = mid;
    }
    g_rowptr[r] = lo;
}

// -------- weight transpose+convert: W[k][n] fp32 -> Wt[n][k] fp16 --------
__global__ void wprep_kernel(const float* __restrict__ W1,
                             const float* __restrict__ W2) {
    int idx = blockIdx.x * 256 + threadIdx.x;   // grid covers 256*256
    {   // W1: 256x256, idx = k*256 + n
        int k = idx >> 8, n = idx & 255;
        g_w1t[(size_t)n * IN_SIZE + k] = __float2half(W1[idx]);
    }
    if (idx < HID_SIZE * OUT_SIZE) {   // W2: 256x64, idx = k*64 + n
        int k = idx >> 6, n = idx & 63;
        g_w2t[(size_t)n * HID_SIZE + k] = __float2half(W2[idx]);
    }
}

// -------- common MMA helpers ---------------------------------------------
__device__ __forceinline__ void mma_h16(float* d, const uint32_t* a, const uint32_t* b) {
    asm volatile(
        "mma.sync.aligned.m16n8k16.row.col.f32.f16.f16.f32 "
        "{%0,%1,%2,%3}, {%4,%5,%6,%7}, {%8,%9}, {%0,%1,%2,%3};\n"
        : "+f"(d[0]), "+f"(d[1]), "+f"(d[2]), "+f"(d[3])
        : "r"(a[0]), "r"(a[1]), "r"(a[2]), "r"(a[3]),
          "r"(b[0]), "r"(b[1]));
}

__device__ __forceinline__ void ldsm_x4(uint32_t* r, const __half* p) {
    uint32_t sa = (uint32_t)__cvta_generic_to_shared(p);
    asm volatile("ldmatrix.sync.aligned.m8n8.x4.shared.b16 {%0,%1,%2,%3}, [%4];"
        : "=r"(r[0]), "=r"(r[1]), "=r"(r[2]), "=r"(r[3]) : "r"(sa));
}

__device__ __forceinline__ void cp16(void* smem_dst, const void* gmem_src) {
    uint32_t d = (uint32_t)__cvta_generic_to_shared(smem_dst);
    asm volatile("cp.async.cg.shared.global [%0], [%1], 16;\n" :: "r"(d), "l"(gmem_src));
}

// ============ GEMM1: inline fp32->fp16 convert, double-buffered (R10) ====
template<int BM, int BN, int N_DIM, int K_DIM>
__global__ __launch_bounds__(256)
void h16_gemm_kernel(int M,
                     const float* __restrict__ A,
                     const __half* __restrict__ Bt,
                     __half* __restrict__ C) {
    constexpr int BK = 32;
    constexpr int WARPS_M = 4, WARPS_N = 2;
    constexpr int MT = BM / (WARPS_M * 16);   // 2
    constexpr int NT = BN / (WARPS_N * 8);    // 8
    constexpr int AST = BK + 8;               // 40-half stride: conflict-free
    constexpr int T = K_DIM / BK;             // 8 k-tiles
    constexpr int A_LD_F = BM * BK / (4 * 256);   // float4/thread: 4
    constexpr int B_LD   = BN * BK / (8 * 256);   // uint4/thread: 2

    __shared__ __half As[2][BM * AST];
    __shared__ __half Bs[2][BN * AST];

    const int tid  = threadIdx.x;
    const int lane = tid & 31;
    const int wid  = tid >> 5;
    const int warp_m = wid % WARPS_M;
    const int warp_n = wid / WARPS_M;
    const int g  = lane >> 2;
    const int tg = lane & 3;
    const int ri = lane & 7;
    const int mi = lane >> 3;

    const int rowBase = blockIdx.y * BM;
    const int colBase = blockIdx.x * BN;
    const int aRow = warp_m * (MT * 16);
    const int bCol = warp_n * (NT * 8);

    float4 afr[A_LD_F];
    uint4  bhr[B_LD];

    float acc[MT][NT][4];
    #pragma unroll
    for (int i = 0; i < MT; i++)
        #pragma unroll
        for (int j = 0; j < NT; j++)
            #pragma unroll
            for (int q = 0; q < 4; q++) acc[i][j][q] = 0.f;

    auto ldgA = [&](int t) {
        int k0 = t * BK;
        #pragma unroll
        for (int i = 0; i < A_LD_F; i++) {
            int idx = tid + i * 256;
            int m = idx >> 3, q = idx & 7;
            int gr = rowBase + m;
            afr[i] = (gr < M)
                ? *(const float4*)(A + (size_t)gr * K_DIM + k0 + q * 4)
                : make_float4(0.f, 0.f, 0.f, 0.f);
        }
    };
    auto stsA = [&](int b) {
        #pragma unroll
        for (int i = 0; i < A_LD_F; i++) {
            int idx = tid + i * 256;
            int m = idx >> 3, q = idx & 7;
            union { uint2 u; __half2 h[2]; } pk;
            pk.h[0] = __floats2half2_rn(afr[i].x, afr[i].y);
            pk.h[1] = __floats2half2_rn(afr[i].z, afr[i].w);
            *(uint2*)&As[b][m * AST + q * 4] = pk.u;
        }
    };
    auto ldgB = [&](int t) {
        int k0 = t * BK;
        #pragma unroll
        for (int i = 0; i < B_LD; i++) {
            int idx = tid + i * 256;
            int n = idx >> 2, q = idx & 3;
            bhr[i] = *(const uint4*)(Bt + (size_t)(colBase + n) * K_DIM + k0 + q * 8);
        }
    };
    auto stsB = [&](int b) {
        #pragma unroll
        for (int i = 0; i < B_LD; i++) {
            int idx = tid + i * 256;
            int n = idx >> 2, q = idx & 3;
            *(uint2*)&Bs[b][n * AST + q * 8]     = make_uint2(bhr[i].x, bhr[i].y);
            *(uint2*)&Bs[b][n * AST + q * 8 + 4] = make_uint2(bhr[i].z, bhr[i].w);
        }
    };
    auto compute = [&](int b) {
        #pragma unroll
        for (int kk = 0; kk < BK; kk += 16) {
            uint32_t af[MT][4];
            #pragma unroll
            for (int mt = 0; mt < MT; mt++) {
                const __half* ap = &As[b][(aRow + mt * 16 + ((mi & 1) << 3) + ri) * AST
                                          + kk + ((mi >> 1) << 3)];
                ldsm_x4(af[mt], ap);
            }
            uint32_t bf[NT][2];
            #pragma unroll
            for (int p = 0; p < NT / 2; p++) {
                const __half* bp = &Bs[b][(bCol + p * 16 + ((mi >> 1) << 3) + ri) * AST
                                          + kk + ((mi & 1) << 3)];
                uint32_t r4[4];
                ldsm_x4(r4, bp);
                bf[p * 2][0] = r4[0]; bf[p * 2][1] = r4[1];
                bf[p * 2 + 1][0] = r4[2]; bf[p * 2 + 1][1] = r4[3];
            }
            #pragma unroll
            for (int nt = 0; nt < NT; nt++)
                #pragma unroll
                for (int mt = 0; mt < MT; mt++)
                    mma_h16(acc[mt][nt], af[mt], bf[nt]);
        }
    };

    ldgA(0); ldgB(0);
    stsA(0); stsB(0);
    __syncthreads();
    ldgA(1); ldgB(1);

    #pragma unroll 2
    for (int t = 0; t < T; t++) {
        compute(t & 1);
        if (t + 1 < T) { stsA((t + 1) & 1); stsB((t + 1) & 1); }
        __syncthreads();
        if (t + 2 < T) { ldgA(t + 2); ldgB(t + 2); }
    }

    #pragma unroll
    for (int mt = 0; mt < MT; mt++) {
        int r0 = rowBase + aRow + mt * 16 + g;
        #pragma unroll
        for (int nt = 0; nt < NT; nt++) {
            int c = colBase + bCol + nt * 8 + tg * 2;
            if (r0 < M) {
                __half2 v = __floats2half2_rn(acc[mt][nt][0], acc[mt][nt][1]);
                *(__half2*)(C + (size_t)r0 * N_DIM + c) = v;
            }
            if (r0 + 8 < M) {
                __half2 v = __floats2half2_rn(acc[mt][nt][2], acc[mt][nt][3]);
                *(__half2*)(C + (size_t)(r0 + 8) * N_DIM + c) = v;
            }
        }
    }
}

// ============ GEMM2: all-fp16, 4-stage cp.async pipeline (R14 form) ======
constexpr int GEMM_STAGES = 4;
constexpr int GEMM_BK = 32;
constexpr int GEMM_AST = GEMM_BK + 8;
constexpr size_t gemm_smem_bytes(int BM, int BN) {
    return (size_t)GEMM_STAGES * (BM + BN) * GEMM_AST * 2;
}

template<int BM, int BN, int N_DIM, int K_DIM>
__global__ __launch_bounds__(256)
void h16_gemm_async(int M,
                    const __half* __restrict__ A,
                    const __half* __restrict__ Bt,
                    __half* __restrict__ C) {
    constexpr int BK = GEMM_BK;
    constexpr int STAGES = GEMM_STAGES;
    constexpr int WARPS_M = 4, WARPS_N = 2;
    constexpr int MT = BM / (WARPS_M * 16);   // 2
    constexpr int NT = BN / (WARPS_N * 8);    // 4 for BN=64
    constexpr int AST = GEMM_AST;
    constexpr int T = K_DIM / BK;             // 8
    constexpr int A_CH = BM * 4 / 256;        // 2
    constexpr int B_CH = BN * 4 / 256;        // 1

    extern __shared__ __half smem[];
    __half* Asm = smem;
    __half* Bsm = smem + (size_t)STAGES * BM * AST;

    const int tid  = threadIdx.x;
    const int lane = tid & 31;
    const int wid  = tid >> 5;
    const int warp_m = wid % WARPS_M;
    const int warp_n = wid / WARPS_M;
    const int g  = lane >> 2;
    const int tg = lane & 3;
    const int ri = lane & 7;
    const int mi = lane >> 3;

    const int rowBase = blockIdx.y * BM;
    const int colBase = blockIdx.x * BN;
    const int aRow = warp_m * (MT * 16);
    const int bCol = warp_n * (NT * 8);

    float acc[MT][NT][4];
    #pragma unroll
    for (int i = 0; i < MT; i++)
        #pragma unroll
        for (int j = 0; j < NT; j++)
            #pragma unroll
            for (int q = 0; q < 4; q++) acc[i][j][q] = 0.f;

    auto issue = [&](int t) {
        int s = t % STAGES;
        int k0 = t * BK;
        __half* Ad = Asm + (size_t)s * (BM * AST);
        __half* Bd = Bsm + (size_t)s * (BN * AST);
        #pragma unroll
        for (int i = 0; i < A_CH; i++) {
            int idx = tid + i * 256;
            int m = idx >> 2, q = idx & 3;
            int gr = rowBase + m;
            if (gr >= M) gr = M - 1;   // clamped read; epilogue guards stores
            cp16(Ad + m * AST + q * 8, A + (size_t)gr * K_DIM + k0 + q * 8);
        }
        #pragma unroll
        for (int i = 0; i < B_CH; i++) {
            int idx = tid + i * 256;
            int n = idx >> 2, q = idx & 3;
            cp16(Bd + n * AST + q * 8, Bt + (size_t)(colBase + n) * K_DIM + k0 + q * 8);
        }
    };

    auto compute = [&](int s) {
        const __half* Ab = Asm + (size_t)s * (BM * AST);
        const __half* Bb = Bsm + (size_t)s * (BN * AST);
        #pragma unroll
        for (int kk = 0; kk < BK; kk += 16) {
            uint32_t af[MT][4];
            #pragma unroll
            for (int mt = 0; mt < MT; mt++) {
                const __half* ap = &Ab[(aRow + mt * 16 + ((mi & 1) << 3) + ri) * AST
                                       + kk + ((mi >> 1) << 3)];
                ldsm_x4(af[mt], ap);
            }
            uint32_t bf[NT][2];
            #pragma unroll
            for (int p = 0; p < NT / 2; p++) {
                const __half* bp = &Bb[(bCol + p * 16 + ((mi >> 1) << 3) + ri) * AST
                                       + kk + ((mi & 1) << 3)];
                uint32_t r4[4];
                ldsm_x4(r4, bp);
                bf[p * 2][0] = r4[0]; bf[p * 2][1] = r4[1];
                bf[p * 2 + 1][0] = r4[2]; bf[p * 2 + 1][1] = r4[3];
            }
            #pragma unroll
            for (int nt = 0; nt < NT; nt++)
                #pragma unroll
                for (int mt = 0; mt < MT; mt++)
                    mma_h16(acc[mt][nt], af[mt], bf[nt]);
        }
    };

    issue(0); asm volatile("cp.async.commit_group;\n" ::);
    issue(1); asm volatile("cp.async.commit_group;\n" ::);
    issue(2); asm volatile("cp.async.commit_group;\n" ::);

    #pragma unroll 4
    for (int t = 0; t < T; t++) {
        asm volatile("cp.async.wait_group 2;\n" ::);
        __syncthreads();
        if (t + 3 < T) issue(t + 3);
        asm volatile("cp.async.commit_group;\n" ::);
        compute(t % STAGES);
    }

    #pragma unroll
    for (int mt = 0; mt < MT; mt++) {
        int r0 = rowBase + aRow + mt * 16 + g;
        #pragma unroll
        for (int nt = 0; nt < NT; nt++) {
            int c = colBase + bCol + nt * 8 + tg * 2;
            if (r0 < M) {
                __half2 v = __floats2half2_rn(acc[mt][nt][0], acc[mt][nt][1]);
                *(__half2*)(C + (size_t)r0 * N_DIM + c) = v;
            }
            if (r0 + 8 < M) {
                __half2 v = __floats2half2_rn(acc[mt][nt][2], acc[mt][nt][3]);
                *(__half2*)(C + (size_t)(r0 + 8) * N_DIM + c) = v;
            }
        }
    }
}

// -------- SpMM layer 1: h = relu(A @ g_xw1 + b1) -------------------------
// TWO warps per row: each warp covers 128 features (4 halves/lane via one
// LDG.64 per edge -> 2 cache lines, 2 wavefronts). Total wavefronts/edge
// unchanged (4) but sourced from independent LDGs in different warps, so
// they drain at the cross-LDG 1.0/cyc rate instead of within-LDG 2.07.
// Per-feature arithmetic identical to R14 (same hfma2 chains, fp32 flush
// every 8 edges) -> bit-identical results. 8 warps = 4 rows per block.
__global__ __launch_bounds__(256)
void spmm1_kernel(const float* __restrict__ ev,
                  const int* __restrict__ col,
                  const float* __restrict__ b1) {
    const int lane = threadIdx.x & 31;
    const int wid  = threadIdx.x >> 5;             // 0..7
    const int r    = blockIdx.x * 4 + (wid >> 1);
    const int half = wid & 1;                      // feature half 0/1
    const int e0 = g_rowptr[r], e1 = g_rowptr[r + 1];

    float acc[4];
    #pragma unroll
    for (int i = 0; i < 4; i++) acc[i] = 0.f;
    __half2 hacc[2];
    #pragma unroll
    for (int i = 0; i < 2; i++) hacc[i] = __float2half2_rn(0.f);

    const __half* base = g_xw1 + half * 128 + lane * 4;
    int e = e0;
    for (; e + 8 <= e1; e += 8) {
        #pragma unroll
        for (int j = 0; j < 8; j++) {
            float v = ev[e + j]; int c = col[e + j];
            __half2 v2 = __float2half2_rn(v);
            uint2 q = *(const uint2*)(base + (size_t)c * HID_SIZE);
            __half2* h = (__half2*)&q;
            hacc[0] = __hfma2(h[0], v2, hacc[0]);
            hacc[1] = __hfma2(h[1], v2, hacc[1]);
        }
        #pragma unroll
        for (int i = 0; i < 2; i++) {
            float2 f = __half22float2(hacc[i]);
            acc[2 * i] += f.x; acc[2 * i + 1] += f.y;
            hacc[i] = __float2half2_rn(0.f);
        }
    }
    for (; e < e1; e++) {
        float v = ev[e]; int c = col[e];
        __half2 v2 = __float2half2_rn(v);
        uint2 q = *(const uint2*)(base + (size_t)c * HID_SIZE);
        __half2* h = (__half2*)&q;
        hacc[0] = __hfma2(h[0], v2, hacc[0]);
        hacc[1] = __hfma2(h[1], v2, hacc[1]);
    }
    #pragma unroll
    for (int i = 0; i < 2; i++) {
        float2 f = __half22float2(hacc[i]);
        acc[2 * i] += f.x; acc[2 * i + 1] += f.y;
    }

    const float* bb = b1 + half * 128 + lane * 4;
    __half2 o[2];
    #pragma unroll
    for (int i = 0; i < 2; i++) {
        float h0 = acc[2 * i]     + bb[2 * i];
        float h1 = acc[2 * i + 1] + bb[2 * i + 1];
        h0 = h0 > 0.f ? h0 : 0.f;
        h1 = h1 > 0.f ? h1 : 0.f;
        o[i] = __floats2half2_rn(h0, h1);
    }
    *(uint2*)(g_h + (size_t)r * HID_SIZE + half * 128 + lane * 4) = *(uint2*)o;
}

// -------- SpMM layer 2: out = A @ g_hw2 + b2 (R14 form) ------------------
// One warp per row (32 lanes x half2 = 64 features), 8 rows per block.
// HFMA2 accumulation, fp32 flush every 8 edges.
__global__ __launch_bounds__(256)
void spmm2_kernel(const float* __restrict__ ev,
                  const int* __restrict__ col,
                  const float* __restrict__ b2,
                  float* __restrict__ out) {
    const int lane = threadIdx.x & 31;
    const int r = blockIdx.x * 8 + (threadIdx.x >> 5);
    const int e0 = g_rowptr[r], e1 = g_rowptr[r + 1];

    float ax = 0.f, ay = 0.f;
    __half2 hacc = __float2half2_rn(0.f);
    const __half2* base = (const __half2*)(g_hw2) + lane;

    auto flush = [&]() {
        float2 f = __half22float2(hacc);
        ax += f.x; ay += f.y;
        hacc = __float2half2_rn(0.f);
    };

    int e = e0;
    for (; e + 8 <= e1; e += 8) {
        #pragma unroll
        for (int j = 0; j < 8; j++) {
            float v = ev[e + j]; int c = col[e + j];
            __half2 v2 = __float2half2_rn(v);
            __half2 q = base[(size_t)c * (OUT_SIZE / 2)];
            hacc = __hfma2(q, v2, hacc);
        }
        flush();
    }
    for (; e < e1; e++) {
        float v = ev[e]; int c = col[e];
        __half2 v2 = __float2half2_rn(v);
        __half2 q = base[(size_t)c * (OUT_SIZE / 2)];
        hacc = __hfma2(q, v2, hacc);
    }
    flush();

    float2 o;
    o.x = ax + b2[lane * 2];
    o.y = ay + b2[lane * 2 + 1];
    *(float2*)(out + (size_t)r * OUT_SIZE + lane * 2) = o;
}

extern "C" void kernel_launch(void* const* d_in, const int* in_sizes, int n_in,
                              void* d_out, int out_size) {
    const float* X   = (const float*)d_in[0];
    const float* ev  = (const float*)d_in[1];
    const float* W1  = (const float*)d_in[2];
    const float* b1  = (const float*)d_in[3];
    const float* W2  = (const float*)d_in[4];
    const float* b2  = (const float*)d_in[5];
    const int*   row = (const int*)  d_in[6];
    const int*   col = (const int*)  d_in[7];
    float* out = (float*)d_out;

    void *p_xw1 = nullptr, *p_h = nullptr, *p_hw2 = nullptr;
    void *p_w1t = nullptr, *p_w2t = nullptr;
    cudaGetSymbolAddress(&p_xw1, g_xw1);
    cudaGetSymbolAddress(&p_h,   g_h);
    cudaGetSymbolAddress(&p_hw2, g_hw2);
    cudaGetSymbolAddress(&p_w1t, g_w1t);
    cudaGetSymbolAddress(&p_w2t, g_w2t);

    constexpr size_t SMEM2 = gemm_smem_bytes(128, 64);   // 61440 B
    cudaFuncSetAttribute(h16_gemm_async<128, 64, OUT_SIZE, HID_SIZE>,
                         cudaFuncAttributeMaxDynamicSharedMemorySize, (int)SMEM2);

    // 1) row_ptr + weight transpose/convert
    {
        int threads = 256;
        int blocks = (N_NODES + 1 + threads - 1) / threads;
        build_rowptr_kernel<<<blocks, threads>>>(row);
        wprep_kernel<<<(IN_SIZE * HID_SIZE) / 256, 256>>>(W1, W2);
    }

    // 2) g_xw1 = X @ W1   (M=100000, N=256, K=256)  inline-convert fp16 MMA
    {
        dim3 grid(HID_SIZE / 128, (N_NODES + 127) / 128);
        h16_gemm_kernel<128, 128, HID_SIZE, IN_SIZE><<<grid, 256>>>(
            N_NODES, X, (const __half*)p_w1t, (__half*)p_xw1);
    }

    // 3) g_h = relu(A @ g_xw1 + b1)   2 warps/row, LDG.64 split gather
    spmm1_kernel<<<N_NODES / 4, 256>>>(ev, col, b1);

    // 4) g_hw2 = g_h @ W2   (M=100000, N=64, K=256)  4-stage cp.async fp16
    {
        dim3 grid(OUT_SIZE / 64, (N_NODES + 127) / 128);
        h16_gemm_async<128, 64, OUT_SIZE, HID_SIZE><<<grid, 256, SMEM2>>>(
            N_NODES, (const __half*)p_h, (const __half*)p_w2t, (__half*)p_hw2);
    }

    // 5) out = A @ g_hw2 + b2   warp-per-row HFMA2 gather
    spmm2_kernel<<<N_NODES / 8, 256>>>(ev, col, b2, out);
}

// round 16
// speedup vs baseline: 1.0503x; 1.0503x over previous
#include <cuda_runtime.h>
#include <cuda_fp16.h>
#include <cstdint>

#define N_NODES 100000
#define N_EDGES 3200000
#define IN_SIZE 256
#define HID_SIZE 256
#define OUT_SIZE 64

// -------- scratch (no allocations allowed -> __device__ globals) --------
__device__ __align__(1024) __half g_xw1[(size_t)N_NODES * HID_SIZE];  // X @ W1
__device__ __align__(1024) __half g_h  [(size_t)N_NODES * HID_SIZE];  // relu(A@XW1+b1)
__device__ __align__(1024) __half g_hw2[(size_t)N_NODES * OUT_SIZE];  // h @ W2
__device__ __align__(1024) __half g_w1t[(size_t)HID_SIZE * IN_SIZE];  // W1^T [n][k]
__device__ __align__(1024) __half g_w2t[(size_t)OUT_SIZE * HID_SIZE]; // W2^T [n][k]
__device__ int    g_rowptr[N_NODES + 1];

// -------- CSR row_ptr from sorted COO row[]: per-node lower_bound --------
__global__ void build_rowptr_kernel(const int* __restrict__ row) {
    int r = blockIdx.x * blockDim.x + threadIdx.x;
    if (r > N_NODES) return;
    int lo = 0, hi = N_EDGES;
    while (lo < hi) {
        int mid = (lo + hi) >> 1;
        if (row[mid] < r) lo = mid + 1; else hi = mid;
    }
    g_rowptr[r] = lo;
}

// -------- weight transpose+convert: W[k][n] fp32 -> Wt[n][k] fp16 --------
__global__ void wprep_kernel(const float* __restrict__ W1,
                             const float* __restrict__ W2) {
    int idx = blockIdx.x * 256 + threadIdx.x;   // grid covers 256*256
    {   // W1: 256x256, idx = k*256 + n
        int k = idx >> 8, n = idx & 255;
        g_w1t[(size_t)n * IN_SIZE + k] = __float2half(W1[idx]);
    }
    if (idx < HID_SIZE * OUT_SIZE) {   // W2: 256x64, idx = k*64 + n
        int k = idx >> 6, n = idx & 63;
        g_w2t[(size_t)n * HID_SIZE + k] = __float2half(W2[idx]);
    }
}

// -------- common MMA helpers ---------------------------------------------
__device__ __forceinline__ void mma_h16(float* d, const uint32_t* a, const uint32_t* b) {
    asm volatile(
        "mma.sync.aligned.m16n8k16.row.col.f32.f16.f16.f32 "
        "{%0,%1,%2,%3}, {%4,%5,%6,%7}, {%8,%9}, {%0,%1,%2,%3};\n"
        : "+f"(d[0]), "+f"(d[1]), "+f"(d[2]), "+f"(d[3])
        : "r"(a[0]), "r"(a[1]), "r"(a[2]), "r"(a[3]),
          "r"(b[0]), "r"(b[1]));
}

__device__ __forceinline__ void ldsm_x4(uint32_t* r, const __half* p) {
    uint32_t sa = (uint32_t)__cvta_generic_to_shared(p);
    asm volatile("ldmatrix.sync.aligned.m8n8.x4.shared.b16 {%0,%1,%2,%3}, [%4];"
        : "=r"(r[0]), "=r"(r[1]), "=r"(r[2]), "=r"(r[3]) : "r"(sa));
}

__device__ __forceinline__ void cp16(void* smem_dst, const void* gmem_src) {
    uint32_t d = (uint32_t)__cvta_generic_to_shared(smem_dst);
    asm volatile("cp.async.cg.shared.global [%0], [%1], 16;\n" :: "r"(d), "l"(gmem_src));
}

__device__ __forceinline__ uint32_t pack_h2(float lo, float hi) {
    __half2 h = __floats2half2_rn(lo, hi);
    return *(uint32_t*)&h;
}

// ============ GEMM1: A fp32 via cp.async (3-stage), convert at frag load =
// BM=128, BN=128, BK=32, 256 threads = 8 warps (4x2).
// A staged raw fp32 (stride 36 floats), fragments via LDS.64 + cvt;
// B fp16 (stride 40 halves) via ldmatrix.
constexpr int G1_STAGES = 3;
constexpr int G1_ASTF = 36;   // fp32 A stride (144B rows, 16B-aligned)
constexpr int G1_ASTB = 40;   // fp16 B stride (80B rows, conflict-free ldsm)
constexpr size_t g1_smem_bytes() {
    return (size_t)G1_STAGES * (128 * G1_ASTF * 4 + 128 * G1_ASTB * 2);
}

template<int N_DIM, int K_DIM>
__global__ __launch_bounds__(256)
void h16_gemm1_async(int M,
                     const float* __restrict__ A,
                     const __half* __restrict__ Bt,
                     __half* __restrict__ C) {
    constexpr int BM = 128, BN = 128, BK = 32;
    constexpr int STAGES = G1_STAGES;
    constexpr int MT = 2, NT = 8;             // 4x2 warps
    constexpr int T = K_DIM / BK;             // 8

    extern __shared__ char smem_raw[];
    float*  Asm = (float*)smem_raw;                                  // STAGES*BM*ASTF
    __half* Bsm = (__half*)(smem_raw + (size_t)STAGES * BM * G1_ASTF * 4);

    const int tid  = threadIdx.x;
    const int lane = tid & 31;
    const int wid  = tid >> 5;
    const int warp_m = wid % 4;
    const int warp_n = wid / 4;
    const int g  = lane >> 2;
    const int tg = lane & 3;
    const int ri = lane & 7;
    const int mi = lane >> 3;

    const int rowBase = blockIdx.y * BM;
    const int colBase = blockIdx.x * BN;
    const int aRow = warp_m * (MT * 16);
    const int bCol = warp_n * (NT * 8);

    float acc[MT][NT][4];
    #pragma unroll
    for (int i = 0; i < MT; i++)
        #pragma unroll
        for (int j = 0; j < NT; j++)
            #pragma unroll
            for (int q = 0; q < 4; q++) acc[i][j][q] = 0.f;

    auto issue = [&](int t) {
        int s = t % STAGES;
        int k0 = t * BK;
        float*  Ad = Asm + (size_t)s * (BM * G1_ASTF);
        __half* Bd = Bsm + (size_t)s * (BN * G1_ASTB);
        // A: BM rows x 32 floats = 8 x 16B chunks per row; 1024 chunks, 4/thread
        #pragma unroll
        for (int i = 0; i < 4; i++) {
            int idx = tid + i * 256;
            int m = idx >> 3, q = idx & 7;
            int gr = rowBase + m;
            if (gr >= M) gr = M - 1;   // clamped read; epilogue guards stores
            cp16(Ad + m * G1_ASTF + q * 4, A + (size_t)gr * K_DIM + k0 + q * 4);
        }
        // B: BN rows x 32 halves = 4 x 16B chunks per row; 512 chunks, 2/thread
        #pragma unroll
        for (int i = 0; i < 2; i++) {
            int idx = tid + i * 256;
            int n = idx >> 2, q = idx & 3;
            cp16(Bd + n * G1_ASTB + q * 8, Bt + (size_t)(colBase + n) * K_DIM + k0 + q * 8);
        }
    };

    auto compute = [&](int s) {
        const float*  Ab = Asm + (size_t)s * (BM * G1_ASTF);
        const __half* Bb = Bsm + (size_t)s * (BN * G1_ASTB);
        #pragma unroll
        for (int kk = 0; kk < BK; kk += 16) {
            // A fragments: LDS.64 fp32 pairs + convert (same values/order as
            // the inline-convert kernel -> bit-identical results)
            uint32_t af[MT][4];
            #pragma unroll
            for (int mt = 0; mt < MT; mt++) {
                const float* ap = Ab + (size_t)(aRow + mt * 16 + g) * G1_ASTF + kk + tg * 2;
                float2 a0 = *(const float2*)(ap);                       // row g,   k..k+1
                float2 a1 = *(const float2*)(ap + 8 * G1_ASTF);         // row g+8, k..k+1
                float2 a2 = *(const float2*)(ap + 8);                   // row g,   k+8..k+9
                float2 a3 = *(const float2*)(ap + 8 * G1_ASTF + 8);     // row g+8, k+8..k+9
                af[mt][0] = pack_h2(a0.x, a0.y);
                af[mt][1] = pack_h2(a1.x, a1.y);
                af[mt][2] = pack_h2(a2.x, a2.y);
                af[mt][3] = pack_h2(a3.x, a3.y);
            }
            uint32_t bf[NT][2];
            #pragma unroll
            for (int p = 0; p < NT / 2; p++) {
                const __half* bp = &Bb[(size_t)(bCol + p * 16 + ((mi >> 1) << 3) + ri) * G1_ASTB
                                       + kk + ((mi & 1) << 3)];
                uint32_t r4[4];
                ldsm_x4(r4, bp);
                bf[p * 2][0] = r4[0]; bf[p * 2][1] = r4[1];
                bf[p * 2 + 1][0] = r4[2]; bf[p * 2 + 1][1] = r4[3];
            }
            #pragma unroll
            for (int nt = 0; nt < NT; nt++)
                #pragma unroll
                for (int mt = 0; mt < MT; mt++)
                    mma_h16(acc[mt][nt], af[mt], bf[nt]);
        }
    };

    // ---- 3-stage pipeline: 2 tiles in flight ----
    issue(0); asm volatile("cp.async.commit_group;\n" ::);
    issue(1); asm volatile("cp.async.commit_group;\n" ::);

    #pragma unroll 3
    for (int t = 0; t < T; t++) {
        asm volatile("cp.async.wait_group 1;\n" ::);   // tile t resident
        __syncthreads();                               // slot t+2 free for reuse
        if (t + 2 < T) issue(t + 2);
        asm volatile("cp.async.commit_group;\n" ::);   // uniform group count
        compute(t % STAGES);
    }

    // ---- epilogue: fp32 acc -> fp16 ----
    #pragma unroll
    for (int mt = 0; mt < MT; mt++) {
        int r0 = rowBase + aRow + mt * 16 + g;
        #pragma unroll
        for (int nt = 0; nt < NT; nt++) {
            int c = colBase + bCol + nt * 8 + tg * 2;
            if (r0 < M) {
                __half2 v = __floats2half2_rn(acc[mt][nt][0], acc[mt][nt][1]);
                *(__half2*)(C + (size_t)r0 * N_DIM + c) = v;
            }
            if (r0 + 8 < M) {
                __half2 v = __floats2half2_rn(acc[mt][nt][2], acc[mt][nt][3]);
                *(__half2*)(C + (size_t)(r0 + 8) * N_DIM + c) = v;
            }
        }
    }
}

// ============ GEMM2: all-fp16, 4-stage cp.async pipeline (R14 form) ======
constexpr int GEMM_STAGES = 4;
constexpr int GEMM_BK = 32;
constexpr int GEMM_AST = GEMM_BK + 8;
constexpr size_t gemm_smem_bytes(int BM, int BN) {
    return (size_t)GEMM_STAGES * (BM + BN) * GEMM_AST * 2;
}

template<int BM, int BN, int N_DIM, int K_DIM>
__global__ __launch_bounds__(256)
void h16_gemm_async(int M,
                    const __half* __restrict__ A,
                    const __half* __restrict__ Bt,
                    __half* __restrict__ C) {
    constexpr int BK = GEMM_BK;
    constexpr int STAGES = GEMM_STAGES;
    constexpr int WARPS_M = 4, WARPS_N = 2;
    constexpr int MT = BM / (WARPS_M * 16);   // 2
    constexpr int NT = BN / (WARPS_N * 8);    // 4 for BN=64
    constexpr int AST = GEMM_AST;
    constexpr int T = K_DIM / BK;             // 8
    constexpr int A_CH = BM * 4 / 256;        // 2
    constexpr int B_CH = BN * 4 / 256;        // 1

    extern __shared__ __half smem[];
    __half* Asm = smem;
    __half* Bsm = smem + (size_t)STAGES * BM * AST;

    const int tid  = threadIdx.x;
    const int lane = tid & 31;
    const int wid  = tid >> 5;
    const int warp_m = wid % WARPS_M;
    const int warp_n = wid / WARPS_M;
    const int g  = lane >> 2;
    const int tg = lane & 3;
    const int ri = lane & 7;
    const int mi = lane >> 3;

    const int rowBase = blockIdx.y * BM;
    const int colBase = blockIdx.x * BN;
    const int aRow = warp_m * (MT * 16);
    const int bCol = warp_n * (NT * 8);

    float acc[MT][NT][4];
    #pragma unroll
    for (int i = 0; i < MT; i++)
        #pragma unroll
        for (int j = 0; j < NT; j++)
            #pragma unroll
            for (int q = 0; q < 4; q++) acc[i][j][q] = 0.f;

    auto issue = [&](int t) {
        int s = t % STAGES;
        int k0 = t * BK;
        __half* Ad = Asm + (size_t)s * (BM * AST);
        __half* Bd = Bsm + (size_t)s * (BN * AST);
        #pragma unroll
        for (int i = 0; i < A_CH; i++) {
            int idx = tid + i * 256;
            int m = idx >> 2, q = idx & 3;
            int gr = rowBase + m;
            if (gr >= M) gr = M - 1;
            cp16(Ad + m * AST + q * 8, A + (size_t)gr * K_DIM + k0 + q * 8);
        }
        #pragma unroll
        for (int i = 0; i < B_CH; i++) {
            int idx = tid + i * 256;
            int n = idx >> 2, q = idx & 3;
            cp16(Bd + n * AST + q * 8, Bt + (size_t)(colBase + n) * K_DIM + k0 + q * 8);
        }
    };

    auto compute = [&](int s) {
        const __half* Ab = Asm + (size_t)s * (BM * AST);
        const __half* Bb = Bsm + (size_t)s * (BN * AST);
        #pragma unroll
        for (int kk = 0; kk < BK; kk += 16) {
            uint32_t af[MT][4];
            #pragma unroll
            for (int mt = 0; mt < MT; mt++) {
                const __half* ap = &Ab[(aRow + mt * 16 + ((mi & 1) << 3) + ri) * AST
                                       + kk + ((mi >> 1) << 3)];
                ldsm_x4(af[mt], ap);
            }
            uint32_t bf[NT][2];
            #pragma unroll
            for (int p = 0; p < NT / 2; p++) {
                const __half* bp = &Bb[(bCol + p * 16 + ((mi >> 1) << 3) + ri) * AST
                                       + kk + ((mi & 1) << 3)];
                uint32_t r4[4];
                ldsm_x4(r4, bp);
                bf[p * 2][0] = r4[0]; bf[p * 2][1] = r4[1];
                bf[p * 2 + 1][0] = r4[2]; bf[p * 2 + 1][1] = r4[3];
            }
            #pragma unroll
            for (int nt = 0; nt < NT; nt++)
                #pragma unroll
                for (int mt = 0; mt < MT; mt++)
                    mma_h16(acc[mt][nt], af[mt], bf[nt]);
        }
    };

    issue(0); asm volatile("cp.async.commit_group;\n" ::);
    issue(1); asm volatile("cp.async.commit_group;\n" ::);
    issue(2); asm volatile("cp.async.commit_group;\n" ::);

    #pragma unroll 4
    for (int t = 0; t < T; t++) {
        asm volatile("cp.async.wait_group 2;\n" ::);
        __syncthreads();
        if (t + 3 < T) issue(t + 3);
        asm volatile("cp.async.commit_group;\n" ::);
        compute(t % STAGES);
    }

    #pragma unroll
    for (int mt = 0; mt < MT; mt++) {
        int r0 = rowBase + aRow + mt * 16 + g;
        #pragma unroll
        for (int nt = 0; nt < NT; nt++) {
            int c = colBase + bCol + nt * 8 + tg * 2;
            if (r0 < M) {
                __half2 v = __floats2half2_rn(acc[mt][nt][0], acc[mt][nt][1]);
                *(__half2*)(C + (size_t)r0 * N_DIM + c) = v;
            }
            if (r0 + 8 < M) {
                __half2 v = __floats2half2_rn(acc[mt][nt][2], acc[mt][nt][3]);
                *(__half2*)(C + (size_t)(r0 + 8) * N_DIM + c) = v;
            }
        }
    }
}

// -------- SpMM layer 1: h = relu(A @ g_xw1 + b1) (R14 locked form) -------
// One warp per row (32 lanes x 8 halves = 256 features), 8 rows per block.
// HFMA2 inner accumulation flushed to fp32 every 8 edges.
__global__ __launch_bounds__(256)
void spmm1_kernel(const float* __restrict__ ev,
                  const int* __restrict__ col,
                  const float* __restrict__ b1) {
    const int lane = threadIdx.x & 31;
    const int r = blockIdx.x * 8 + (threadIdx.x >> 5);
    const int e0 = g_rowptr[r], e1 = g_rowptr[r + 1];

    float acc[8];
    #pragma unroll
    for (int i = 0; i < 8; i++) acc[i] = 0.f;
    __half2 hacc[4];
    #pragma unroll
    for (int i = 0; i < 4; i++) hacc[i] = __float2half2_rn(0.f);

    const __half* base = g_xw1 + lane * 8;
    int e = e0;
    for (; e + 8 <= e1; e += 8) {
        #pragma unroll
        for (int j = 0; j < 8; j++) {
            float v = ev[e + j]; int c = col[e + j];
            __half2 v2 = __float2half2_rn(v);
            uint4 q = *(const uint4*)(base + (size_t)c * HID_SIZE);
            __half2* h = (__half2*)&q;
            hacc[0] = __hfma2(h[0], v2, hacc[0]);
            hacc[1] = __hfma2(h[1], v2, hacc[1]);
            hacc[2] = __hfma2(h[2], v2, hacc[2]);
            hacc[3] = __hfma2(h[3], v2, hacc[3]);
        }
        #pragma unroll
        for (int i = 0; i < 4; i++) {
            float2 f = __half22float2(hacc[i]);
            acc[2 * i] += f.x; acc[2 * i + 1] += f.y;
            hacc[i] = __float2half2_rn(0.f);
        }
    }
    for (; e < e1; e++) {
        float v = ev[e]; int c = col[e];
        __half2 v2 = __float2half2_rn(v);
        uint4 q = *(const uint4*)(base + (size_t)c * HID_SIZE);
        __half2* h = (__half2*)&q;
        hacc[0] = __hfma2(h[0], v2, hacc[0]);
        hacc[1] = __hfma2(h[1], v2, hacc[1]);
        hacc[2] = __hfma2(h[2], v2, hacc[2]);
        hacc[3] = __hfma2(h[3], v2, hacc[3]);
    }
    #pragma unroll
    for (int i = 0; i < 4; i++) {
        float2 f = __half22float2(hacc[i]);
        acc[2 * i] += f.x; acc[2 * i + 1] += f.y;
    }

    __half2 o[4];
    #pragma unroll
    for (int i = 0; i < 4; i++) {
        float h0 = acc[2 * i]     + b1[lane * 8 + 2 * i];
        float h1 = acc[2 * i + 1] + b1[lane * 8 + 2 * i + 1];
        h0 = h0 > 0.f ? h0 : 0.f;
        h1 = h1 > 0.f ? h1 : 0.f;
        o[i] = __floats2half2_rn(h0, h1);
    }
    *(uint4*)(g_h + (size_t)r * HID_SIZE + lane * 8) = *(uint4*)o;
}

// -------- SpMM layer 2: out = A @ g_hw2 + b2 (R14 form) ------------------
__global__ __launch_bounds__(256)
void spmm2_kernel(const float* __restrict__ ev,
                  const int* __restrict__ col,
                  const float* __restrict__ b2,
                  float* __restrict__ out) {
    const int lane = threadIdx.x & 31;
    const int r = blockIdx.x * 8 + (threadIdx.x >> 5);
    const int e0 = g_rowptr[r], e1 = g_rowptr[r + 1];

    float ax = 0.f, ay = 0.f;
    __half2 hacc = __float2half2_rn(0.f);
    const __half2* base = (const __half2*)(g_hw2) + lane;

    auto flush = [&]() {
        float2 f = __half22float2(hacc);
        ax += f.x; ay += f.y;
        hacc = __float2half2_rn(0.f);
    };

    int e = e0;
    for (; e + 8 <= e1; e += 8) {
        #pragma unroll
        for (int j = 0; j < 8; j++) {
            float v = ev[e + j]; int c = col[e + j];
            __half2 v2 = __float2half2_rn(v);
            __half2 q = base[(size_t)c * (OUT_SIZE / 2)];
            hacc = __hfma2(q, v2, hacc);
        }
        flush();
    }
    for (; e < e1; e++) {
        float v = ev[e]; int c = col[e];
        __half2 v2 = __float2half2_rn(v);
        __half2 q = base[(size_t)c * (OUT_SIZE / 2)];
        hacc = __hfma2(q, v2, hacc);
    }
    flush();

    float2 o;
    o.x = ax + b2[lane * 2];
    o.y = ay + b2[lane * 2 + 1];
    *(float2*)(out + (size_t)r * OUT_SIZE + lane * 2) = o;
}

extern "C" void kernel_launch(void* const* d_in, const int* in_sizes, int n_in,
                              void* d_out, int out_size) {
    const float* X   = (const float*)d_in[0];
    const float* ev  = (const float*)d_in[1];
    const float* W1  = (const float*)d_in[2];
    const float* b1  = (const float*)d_in[3];
    const float* W2  = (const float*)d_in[4];
    const float* b2  = (const float*)d_in[5];
    const int*   row = (const int*)  d_in[6];
    const int*   col = (const int*)  d_in[7];
    float* out = (float*)d_out;

    void *p_xw1 = nullptr, *p_h = nullptr, *p_hw2 = nullptr;
    void *p_w1t = nullptr, *p_w2t = nullptr;
    cudaGetSymbolAddress(&p_xw1, g_xw1);
    cudaGetSymbolAddress(&p_h,   g_h);
    cudaGetSymbolAddress(&p_hw2, g_hw2);
    cudaGetSymbolAddress(&p_w1t, g_w1t);
    cudaGetSymbolAddress(&p_w2t, g_w2t);

    constexpr size_t SMEM1 = g1_smem_bytes();            // 86016 B
    constexpr size_t SMEM2 = gemm_smem_bytes(128, 64);   // 61440 B
    cudaFuncSetAttribute(h16_gemm1_async<HID_SIZE, IN_SIZE>,
                         cudaFuncAttributeMaxDynamicSharedMemorySize, (int)SMEM1);
    cudaFuncSetAttribute(h16_gemm_async<128, 64, OUT_SIZE, HID_SIZE>,
                         cudaFuncAttributeMaxDynamicSharedMemorySize, (int)SMEM2);

    // 1) row_ptr + weight transpose/convert
    {
        int threads = 256;
        int blocks = (N_NODES + 1 + threads - 1) / threads;
        build_rowptr_kernel<<<blocks, threads>>>(row);
        wprep_kernel<<<(IN_SIZE * HID_SIZE) / 256, 256>>>(W1, W2);
    }

    // 2) g_xw1 = X @ W1   (M=100000, N=256, K=256)  fp32-A cp.async pipeline
    {
        dim3 grid(HID_SIZE / 128, (N_NODES + 127) / 128);
        h16_gemm1_async<HID_SIZE, IN_SIZE><<<grid, 256, SMEM1>>>(
            N_NODES, X, (const __half*)p_w1t, (__half*)p_xw1);
    }

    // 3) g_h = relu(A @ g_xw1 + b1)   warp-per-row HFMA2 gather (locked)
    spmm1_kernel<<<N_NODES / 8, 256>>>(ev, col, b1);

    // 4) g_hw2 = g_h @ W2   (M=100000, N=64, K=256)  4-stage cp.async fp16
    {
        dim3 grid(OUT_SIZE / 64, (N_NODES + 127) / 128);
        h16_gemm_async<128, 64, OUT_SIZE, HID_SIZE><<<grid, 256, SMEM2>>>(
            N_NODES, (const __half*)p_h, (const __half*)p_w2t, (__half*)p_hw2);
    }

    // 5) out = A @ g_hw2 + b2   warp-per-row HFMA2 gather
    spmm2_kernel<<<N_NODES / 8, 256>>>(ev, col, b2, out);
}